// round 13
// baseline (speedup 1.0000x reference)
#include <cuda_runtime.h>

typedef unsigned long long u64;

__device__ __forceinline__ void fma2(u64& d, u64 a, u64 b) {
    asm("fma.rn.f32x2 %0, %1, %2, %0;" : "+l"(d) : "l"(a), "l"(b));
}

// Separable tap-set fold, fully unrolled, compile-time indices only.
// o[rd*9+rh*3+rw] = sc * sum_{kd in T(rd), kh in T(rh), kw in T(rw)} a[kd*9+kh*3+kw]
// with T(0)={1,2}, T(1)={0,1,2}, T(2)={0}.
__device__ __forceinline__ void fold27(const float* __restrict__ a, float sc,
                                       float* __restrict__ o) {
    float c[27];
#pragma unroll
    for (int j = 0; j < 9; ++j) {
        float i0 = a[3 * j], i1 = a[3 * j + 1], i2 = a[3 * j + 2];
        float t = i1 + i2;
        c[3 * j + 0] = t; c[3 * j + 1] = t + i0; c[3 * j + 2] = i0;
    }
    float d[27];
#pragma unroll
    for (int kd = 0; kd < 3; ++kd)
#pragma unroll
        for (int rw = 0; rw < 3; ++rw) {
            float r0 = c[(3 * kd + 0) * 3 + rw];
            float r1 = c[(3 * kd + 1) * 3 + rw];
            float r2 = c[(3 * kd + 2) * 3 + rw];
            float t = r1 + r2;
            d[(kd * 3 + 0) * 3 + rw] = t;
            d[(kd * 3 + 1) * 3 + rw] = t + r0;
            d[(kd * 3 + 2) * 3 + rw] = r0;
        }
#pragma unroll
    for (int rh = 0; rh < 3; ++rh)
#pragma unroll
        for (int rw = 0; rw < 3; ++rw) {
            float r0 = d[(0 * 3 + rh) * 3 + rw];
            float r1 = d[(1 * 3 + rh) * 3 + rw];
            float r2 = d[(2 * 3 + rh) * 3 + rw];
            float t = r1 + r2;
            o[(0 * 3 + rh) * 3 + rw] = t * sc;
            o[(1 * 3 + rh) * 3 + rw] = (t + r0) * sc;
            o[(2 * 3 + rh) * 3 + rw] = r0 * sc;
        }
}

// ---------------------------------------------------------------------------
// Single fused kernel. 296 blocks x 512 threads, 2 blocks/SM (32 warps/SM).
// Folded weights live in SMEM (one copy per block) so per-thread regs stay
// under 64 and the RF admits 1024 threads/SM.
//
// Iter it (0,1): tile A = bid + it*592 (warps 0-7), tile B = A + 296
// (warps 8-15; invalid on it=1 unless bid<80). 80*4 + 216*3 = 968 tiles.
// Warp: pair p = wid&7, slot s = wid>>3; per rr: 3 conflict-free LDS.64
// weight loads + streamed f32x2 FMA over 11 ow accs; cross-warp reduce via
// red smem; next iter's x LDGs issue before the store phase (latency hidden).
// ---------------------------------------------------------------------------
__global__ __launch_bounds__(512, 2)
void conv_fused_kernel(const float* __restrict__ x,
                       const float* __restrict__ wsrc,
                       const float* __restrict__ bias,
                       const float* __restrict__ gamma,
                       const float* __restrict__ beta,
                       const float* __restrict__ mean,
                       const float* __restrict__ var,
                       float* __restrict__ out) {
    extern __shared__ __align__(16) char sm[];
    u64*   wsm = reinterpret_cast<u64*>(sm);             // 8*27*32 u64 = 55296 B
    u64*   xs  = reinterpret_cast<u64*>(sm + 55296);     // 2 slots * 1728 u64 = 27648 B
    float* red = reinterpret_cast<float*>(sm + 82944);   // 16*352 floats = 22528 B

    const int tid  = threadIdx.x;
    const int lane = tid & 31;   // co
    const int wid  = tid >> 5;
    const int bid  = blockIdx.x;

    const float scale = __ldg(&gamma[lane]) * rsqrtf(__ldg(&var[lane]) + 1e-5f);
    const float cb = __ldg(&bias[lane]) * scale + __ldg(&beta[lane])
                   - __ldg(&mean[lane]) * scale;
    const float sc64 = scale * (1.f / 64.f);

    // ================= in-kernel weight fold (warps 0-7) =================
    if (wid < 8) {
        float* scr = reinterpret_cast<float*>(xs) + wid * 864;   // 3456 B/warp
        float* wb = reinterpret_cast<float*>(wsm) + (wid * 27 * 32 + lane) * 2;
#pragma unroll 1
        for (int ph = 0; ph < 2; ++ph) {   // ci = 2*wid + ph
            const float4* src = reinterpret_cast<const float4*>(
                wsrc + (size_t)(2 * wid + ph) * 864);
            float4* dst = reinterpret_cast<float4*>(scr);
#pragma unroll
            for (int k = 0; k < 7; ++k) {
                int i = lane + k * 32;
                if (i < 216) dst[i] = __ldg(src + i);
            }
            __syncwarp();
            float a[27];
            const float* ap = scr + lane * 27;    // stride 27 vs 32 banks: clean
#pragma unroll
            for (int k = 0; k < 27; ++k) a[k] = ap[k];
            float o[27];
            fold27(a, sc64, o);
#pragma unroll
            for (int r = 0; r < 27; ++r) wb[r * 64 + ph] = o[r];
            __syncwarp();
        }
    }
    __syncthreads();   // wsm ready; xs scratch free

    // ================= staging task decode (hoisted) =================
    // 864 tasks (2 tiles x 432); thread does task tid, and tid+512 if tid<352.
    const int s1  = tid >= 432;
    const int uu1 = tid - s1 * 432;
    const int p1  = uu1 / 54, r21 = uu1 - p1 * 54;
    const int rr1 = r21 / 6,  q1  = r21 - rr1 * 6;
    const int srcO1 = 2 * p1 * 13824 + (rr1 / 3) * 576 + (rr1 % 3) * 24 + 4 * q1;
    const int dst1  = s1 * 864 + (p1 * 9 + rr1) * 12 + 2 * q1;   // float4 idx

    const bool t2v = tid < 352;                  // task2 always slot 1
    const int uu2 = tid + 80;                    // (tid+512)-432
    const int p2  = uu2 / 54, r22 = uu2 - p2 * 54;
    const int rr2 = r22 / 6,  q2  = r22 - rr2 * 6;
    const int srcO2 = 2 * p2 * 13824 + (rr2 / 3) * 576 + (rr2 % 3) * 24 + 4 * q2;
    const int dst2  = 864 + (p2 * 9 + rr2) * 12 + 2 * q2;

    const bool validB1 = (bid < 80);   // iter1's tile B exists only for bid<80

    // ================= prologue: stage iter0 tiles (both valid) ==========
    {
        int gA = bid, gB = bid + 296;
        int bA = gA / 121, rA = gA - bA * 121;
        int bB = gB / 121, rB = gB - bB * 121;
        const float* xbA = x + (size_t)bA * 221184 + 2 * (rA / 11) * 576 + 2 * (rA % 11) * 24;
        const float* xbB = x + (size_t)bB * 221184 + 2 * (rB / 11) * 576 + 2 * (rB % 11) * 24;
        const float* sA = s1 ? xbB : xbA;
        float4 A1 = __ldg(reinterpret_cast<const float4*>(sA + srcO1));
        float4 B1 = __ldg(reinterpret_cast<const float4*>(sA + srcO1 + 13824));
        float4* d = reinterpret_cast<float4*>(xs);
        d[dst1]     = make_float4(A1.x, B1.x, A1.y, B1.y);
        d[dst1 + 1] = make_float4(A1.z, B1.z, A1.w, B1.w);
        if (t2v) {
            float4 A2 = __ldg(reinterpret_cast<const float4*>(xbB + srcO2));
            float4 B2 = __ldg(reinterpret_cast<const float4*>(xbB + srcO2 + 13824));
            d[dst2]     = make_float4(A2.x, B2.x, A2.y, B2.y);
            d[dst2 + 1] = make_float4(A2.z, B2.z, A2.w, B2.w);
        }
    }
    __syncthreads();

    // ================= main loop: 2 iterations of 2 tiles ================
#pragma unroll 1
    for (int it = 0; it < 2; ++it) {
        const bool validB = (it == 0) || validB1;
        const int gA = bid + it * 592, gB = gA + 296;
        const int bA = gA / 121, rA = gA - bA * 121, odA = rA / 11, ohA = rA - odA * 11;
        const int bB = gB / 121, rB = gB - bB * 121, odB = rB / 11, ohB = rB - odB * 11;

        // ---- compute ----
        {
            const int s = wid >> 3, p = wid & 7;
            if (s == 0 || validB) {
                const u64* xw = xs + s * 1728 + p * 216;
                const u64* wp = wsm + p * 864 + lane;
                u64 acc[11];
#pragma unroll
                for (int i = 0; i < 11; ++i) acc[i] = 0ull;
#pragma unroll
                for (int rr = 0; rr < 9; ++rr) {
                    u64 w0 = wp[(3 * rr + 0) * 32];
                    u64 w1 = wp[(3 * rr + 1) * 32];
                    u64 w2 = wp[(3 * rr + 2) * 32];
                    const ulonglong2* rp =
                        reinterpret_cast<const ulonglong2*>(xw + rr * 24);
                    ulonglong2 tt = rp[0];
                    u64 x0 = tt.x, x1 = tt.y;
#pragma unroll
                    for (int ow = 0; ow < 11; ++ow) {
                        ulonglong2 tn = rp[ow + 1];
                        fma2(acc[ow], w0, x0);
                        fma2(acc[ow], w1, x1);
                        fma2(acc[ow], w2, tn.x);
                        x0 = tn.x;
                        x1 = tn.y;
                    }
                }
#pragma unroll
                for (int ow = 0; ow < 11; ++ow) {
                    float lo, hi;
                    asm("mov.b64 {%0, %1}, %2;" : "=f"(lo), "=f"(hi) : "l"(acc[ow]));
                    red[wid * 352 + ow * 32 + lane] = lo + hi;
                }
            }
        }
        __syncthreads();   // red ready; xs reads done

        // ---- issue next iter's x loads (it==0 only) ----
        float4 A1v, B1v, A2v, B2v;
        bool st1 = false, st2 = false;
        if (it == 0) {
            int gA1 = bid + 592, gB1 = gA1 + 296;
            int bA1 = gA1 / 121, rA1 = gA1 - bA1 * 121;
            int bB1 = gB1 / 121, rB1 = gB1 - bB1 * 121;
            const float* xbA = x + (size_t)bA1 * 221184 + 2 * (rA1 / 11) * 576 + 2 * (rA1 % 11) * 24;
            const float* xbB = x + (size_t)bB1 * 221184 + 2 * (rB1 / 11) * 576 + 2 * (rB1 % 11) * 24;
            st1 = (s1 == 0) || validB1;
            st2 = t2v && validB1;
            if (st1) {
                const float* sA = s1 ? xbB : xbA;
                A1v = __ldg(reinterpret_cast<const float4*>(sA + srcO1));
                B1v = __ldg(reinterpret_cast<const float4*>(sA + srcO1 + 13824));
            }
            if (st2) {
                A2v = __ldg(reinterpret_cast<const float4*>(xbB + srcO2));
                B2v = __ldg(reinterpret_cast<const float4*>(xbB + srcO2 + 13824));
            }
        }

        // ---- store current outputs (fills the LDG latency window) ----
        {
            int s = tid >= 352;
            int j = tid - s * 352;
            if (s == 0 || validB) {
                float sum = cb;
#pragma unroll
                for (int w = 0; w < 8; ++w) sum += red[(s * 8 + w) * 352 + j];
                int b = s ? bB : bA, od = s ? odB : odA, oh = s ? ohB : ohA;
                out[((size_t)(b * 32 + lane)) * 1331 + od * 121 + oh * 11 + (j >> 5)] = sum;
            }
            if (tid < 192 && validB) {
                int j2 = tid + 160;   // slot 1, ow 5..10
                float sum = cb;
#pragma unroll
                for (int w = 0; w < 8; ++w) sum += red[(8 + w) * 352 + j2];
                out[((size_t)(bB * 32 + lane)) * 1331 + odB * 121 + ohB * 11 + (j2 >> 5)] = sum;
            }
        }

        // ---- interleave-store next iter's tiles into xs ----
        if (st1) {
            float4* d = reinterpret_cast<float4*>(xs);
            d[dst1]     = make_float4(A1v.x, B1v.x, A1v.y, B1v.y);
            d[dst1 + 1] = make_float4(A1v.z, B1v.z, A1v.w, B1v.w);
        }
        if (st2) {
            float4* d = reinterpret_cast<float4*>(xs);
            d[dst2]     = make_float4(A2v.x, B2v.x, A2v.y, B2v.y);
            d[dst2 + 1] = make_float4(A2v.z, B2v.z, A2v.w, B2v.w);
        }
        __syncthreads();   // red consumed + new xs visible
    }
}

extern "C" void kernel_launch(void* const* d_in, const int* in_sizes, int n_in,
                              void* d_out, int out_size) {
    const float* x     = (const float*)d_in[0];
    const float* w     = (const float*)d_in[1];
    const float* bias  = (const float*)d_in[2];
    const float* gamma = (const float*)d_in[3];
    const float* beta  = (const float*)d_in[4];
    const float* mean  = (const float*)d_in[5];
    const float* var   = (const float*)d_in[6];
    float* out = (float*)d_out;

    cudaFuncSetAttribute(conv_fused_kernel,
                         cudaFuncAttributeMaxDynamicSharedMemorySize, 105472);
    conv_fused_kernel<<<296, 512, 105472>>>(x, w, bias, gamma, beta, mean, var, out);
}